// round 2
// baseline (speedup 1.0000x reference)
#include <cuda_runtime.h>

#define NN 20000      // nodes
#define NE 100000     // edges
#define NF 64         // node feature dim (in)
#define EFD 32        // edge feature dim
#define FH 128        // heads * out_dim = 2*64
#define NH 2          // heads
#define DH 64         // out dim per head

// ---------------- scratch (device globals; no allocation allowed) ----------
__device__ float g_ft[NN * FH];          // node features after fc  [N, H*D]
__device__ float g_fe[NE * FH];          // edge features after fc  [E, H*D]
__device__ float g_el[NN * NH];
__device__ float g_er[NN * NH];
__device__ float g_ee[NE * NH];
__device__ float g_p [NE * NH];          // logits, then exp(p)
__device__ unsigned int g_m[NN * NH];    // segment max (ordered-uint float)
__device__ float g_s [NN * NH];          // segment sum
__device__ float g_acc[NN * FH];         // message accumulator
__device__ float g_h [NN * NF];          // inter-layer features
__device__ float g_h2[NN * NF];

// ordered-uint encoding for float atomicMax
__device__ __forceinline__ unsigned int fenc(float f) {
    unsigned int u = __float_as_uint(f);
    return (u & 0x80000000u) ? ~u : (u | 0x80000000u);
}
__device__ __forceinline__ float fdec(unsigned int u) {
    return __uint_as_float((u & 0x80000000u) ? (u ^ 0x80000000u) : ~u);
}

// ---------------- node transform: ft = x @ Wn, el/er attention dots --------
__global__ __launch_bounds__(128) void node_kernel(
        const float* __restrict__ x, const float* __restrict__ Wn,
        const float* __restrict__ al, const float* __restrict__ ar)
{
    const int c = threadIdx.x;                 // output column 0..127
    const int n0 = blockIdx.x * 16;
    float w[NF];
#pragma unroll
    for (int k = 0; k < NF; k++) w[k] = Wn[k * FH + c];   // coalesced across c
    const float alc = al[c], arc = ar[c];

    __shared__ float sx[16][NF];
#pragma unroll
    for (int i = 0; i < 8; i++) {              // 16*64 = 8*128
        int idx = i * 128 + c;
        sx[idx >> 6][idx & 63] = x[n0 * NF + idx];
    }
    __syncthreads();

    __shared__ float swl[4], swr[4];
    const int wid = c >> 5, lane = c & 31;
    for (int i = 0; i < 16; i++) {
        const int n = n0 + i;
        float f = 0.f;
#pragma unroll
        for (int k = 0; k < NF; k++) f = fmaf(sx[i][k], w[k], f);
        g_ft[n * FH + c] = f;
        float vl = f * alc, vr = f * arc;
#pragma unroll
        for (int o = 16; o; o >>= 1) {
            vl += __shfl_down_sync(0xffffffffu, vl, o);
            vr += __shfl_down_sync(0xffffffffu, vr, o);
        }
        if (lane == 0) { swl[wid] = vl; swr[wid] = vr; }
        __syncthreads();
        if (c < NH) {
            g_el[n * NH + c] = swl[2 * c] + swl[2 * c + 1];
            g_er[n * NH + c] = swr[2 * c] + swr[2 * c + 1];
        }
        __syncthreads();
    }
}

// ---------------- edge transform: fe = ef @ We, ee attention dot -----------
__global__ __launch_bounds__(128) void edge_kernel(
        const float* __restrict__ ef, const float* __restrict__ We,
        const float* __restrict__ ae)
{
    const int c = threadIdx.x;
    const int e0 = blockIdx.x * 16;
    float w[EFD];
#pragma unroll
    for (int k = 0; k < EFD; k++) w[k] = We[k * FH + c];
    const float aec = ae[c];

    __shared__ float sx[16][EFD];
#pragma unroll
    for (int i = 0; i < 4; i++) {              // 16*32 = 4*128
        int idx = i * 128 + c;
        sx[idx >> 5][idx & 31] = ef[e0 * EFD + idx];
    }
    __syncthreads();

    __shared__ float swv[4];
    const int wid = c >> 5, lane = c & 31;
    for (int i = 0; i < 16; i++) {
        const int e = e0 + i;
        float f = 0.f;
#pragma unroll
        for (int k = 0; k < EFD; k++) f = fmaf(sx[i][k], w[k], f);
        g_fe[e * FH + c] = f;
        float v = f * aec;
#pragma unroll
        for (int o = 16; o; o >>= 1) v += __shfl_down_sync(0xffffffffu, v, o);
        if (lane == 0) swv[wid] = v;
        __syncthreads();
        if (c < NH) g_ee[e * NH + c] = swv[2 * c] + swv[2 * c + 1];
        __syncthreads();
    }
}

// ---------------- per-layer init -------------------------------------------
__global__ void init_kernel()
{
    const int i = blockIdx.x * blockDim.x + threadIdx.x;
    if (i < NN * FH) g_acc[i] = 0.f;
    if (i < NN * NH) { g_m[i] = 0x007FFFFFu /* fenc(-inf) */; g_s[i] = 0.f; }
}

// ---------------- logits + segment max -------------------------------------
__global__ void logits_kernel(const int* __restrict__ src, const int* __restrict__ dst)
{
    const int i = blockIdx.x * blockDim.x + threadIdx.x;   // e*2 + h
    if (i >= NE * NH) return;
    const int e = i >> 1, h = i & 1;
    const int dn = dst[e];
    float l = g_el[src[e] * NH + h] + g_er[dn * NH + h] + g_ee[i];
    l = (l > 0.f) ? l : 0.2f * l;                          // leaky_relu(0.2)
    g_p[i] = l;
    atomicMax(&g_m[dn * NH + h], fenc(l));
}

// ---------------- exp + segment sum -----------------------------------------
__global__ void expsum_kernel(const int* __restrict__ dst)
{
    const int i = blockIdx.x * blockDim.x + threadIdx.x;
    if (i >= NE * NH) return;
    const int e = i >> 1, h = i & 1;
    const int dn = dst[e];
    const float pv = __expf(g_p[i] - fdec(g_m[dn * NH + h]));
    g_p[i] = pv;
    atomicAdd(&g_s[dn * NH + h], pv);
}

// ---------------- message scatter -------------------------------------------
__global__ void msg_kernel(const int* __restrict__ src, const int* __restrict__ dst)
{
    const int i = blockIdx.x * blockDim.x + threadIdx.x;   // e*128 + c
    if (i >= NE * FH) return;
    const int e = i >> 7, c = i & 127, h = c >> 6;
    const int sn = src[e], dn = dst[e];
    const float a = g_p[e * NH + h] / g_s[dn * NH + h];
    const float v = (g_ft[sn * FH + c] + g_fe[i]) * a;
    atomicAdd(&g_acc[dn * FH + c], v);
}

// ---------------- finalize: + bias, mean over heads -------------------------
__global__ void fin_kernel(const float* __restrict__ b, float* __restrict__ hout)
{
    const int i = blockIdx.x * blockDim.x + threadIdx.x;   // n*64 + d
    if (i >= NN * DH) return;
    const int n = i >> 6, d = i & 63;
    hout[i] = 0.5f * ((g_acc[n * FH + d] + b[d]) +
                      (g_acc[n * FH + 64 + d] + b[64 + d]));
}

// ---------------- encoder-to-decoder: h @ W^T (W is [64,64] row-major) ------
__global__ __launch_bounds__(64) void e2d_kernel(
        const float* __restrict__ hin, const float* __restrict__ W,
        float* __restrict__ hout)
{
    const int j = threadIdx.x;                 // 0..63
    const int n0 = blockIdx.x * 16;
    float w[64];
#pragma unroll
    for (int k = 0; k < 64; k++) w[k] = W[j * 64 + k];
    __shared__ float sx[16][64];
    for (int i = j; i < 16 * 64; i += 64)
        sx[i >> 6][i & 63] = hin[n0 * 64 + i];
    __syncthreads();
    for (int i = 0; i < 16; i++) {
        float acc = 0.f;
#pragma unroll
        for (int k = 0; k < 64; k++) acc = fmaf(sx[i][k], w[k], acc);
        hout[(n0 + i) * 64 + j] = acc;
    }
}

// ---------------- host-side driver ------------------------------------------
static void run_layer(const float* xin, const float* ef,
                      const int* src, const int* dst,
                      const float* Wn, const float* We,
                      const float* al, const float* ar,
                      const float* ae, const float* b, float* hout)
{
    node_kernel<<<NN / 16, 128>>>(xin, Wn, al, ar);
    edge_kernel<<<NE / 16, 128>>>(ef, We, ae);
    init_kernel<<<(NN * FH + 255) / 256, 256>>>();
    logits_kernel<<<(NE * NH + 255) / 256, 256>>>(src, dst);
    expsum_kernel<<<(NE * NH + 255) / 256, 256>>>(dst);
    msg_kernel<<<(NE * FH + 255) / 256, 256>>>(src, dst);
    fin_kernel<<<(NN * DH + 255) / 256, 256>>>(b, hout);
}

extern "C" void kernel_launch(void* const* d_in, const int* in_sizes, int n_in,
                              void* d_out, int out_size)
{
    const float* x   = (const float*)d_in[0];
    const float* e   = (const float*)d_in[1];
    const int*   src = (const int*)  d_in[2];
    const int*   dst = (const int*)  d_in[3];

    // Only the LAST snapshot contributes to the output (decoded[-1]).
    const int S = in_sizes[0] / (NN * NF);
    const float* xs = x   + (size_t)(S - 1) * NN * NF;
    const float* es = e   + (size_t)(S - 1) * NE * EFD;
    const int*   ss = src + (size_t)(S - 1) * NE;
    const int*   ds = dst + (size_t)(S - 1) * NE;

    void *ph = nullptr, *ph2 = nullptr;
    cudaGetSymbolAddress(&ph,  g_h);
    cudaGetSymbolAddress(&ph2, g_h2);
    float* h  = (float*)ph;
    float* h2 = (float*)ph2;

    // Input order follows setup_inputs() dict insertion order:
    //   0:x 1:e 2:src 3:dst
    //   4..9:   enc0 {Wn,We,al,ar,ae,b}
    //   10..15: enc1
    //   16..21: dec0
    //   22..27: dec1
    //   28:     W_e2d   (appended AFTER the layer loop)

    // encoder layer 0
    run_layer(xs, es, ss, ds,
              (const float*)d_in[4],  (const float*)d_in[5],
              (const float*)d_in[6],  (const float*)d_in[7],
              (const float*)d_in[8],  (const float*)d_in[9],  h);
    // encoder layer 1
    run_layer(h, es, ss, ds,
              (const float*)d_in[10], (const float*)d_in[11],
              (const float*)d_in[12], (const float*)d_in[13],
              (const float*)d_in[14], (const float*)d_in[15], h2);
    // encoder_to_decoder (W_e2d = d_in[28])
    e2d_kernel<<<NN / 16, 64>>>(h2, (const float*)d_in[28], h);
    // decoder layer 0: d_in[16..21]
    run_layer(h, es, ss, ds,
              (const float*)d_in[16], (const float*)d_in[17],
              (const float*)d_in[18], (const float*)d_in[19],
              (const float*)d_in[20], (const float*)d_in[21], h2);
    // decoder layer 1: d_in[22..27] -> final output
    run_layer(h2, es, ss, ds,
              (const float*)d_in[22], (const float*)d_in[23],
              (const float*)d_in[24], (const float*)d_in[25],
              (const float*)d_in[26], (const float*)d_in[27], (float*)d_out);
}

// round 3
// speedup vs baseline: 1.4023x; 1.4023x over previous
#include <cuda_runtime.h>

#define NN 20000      // nodes
#define NE 100000     // edges
#define NF 64         // node feature dim (in)
#define EFD 32        // edge feature dim
#define FH 128        // heads * out_dim = 2*64
#define NH 2          // heads
#define DH 64         // out dim per head

// ---------------- scratch (device globals; no allocation allowed) ----------
__device__ __align__(16) float g_ft[NN * FH];   // node features after fc  [N, H*D]
__device__ __align__(16) float g_fe[NE * FH];   // edge features after fc  [E, H*D]
__device__ __align__(16) float g_el[NN * NH];
__device__ __align__(16) float g_er[NN * NH];
__device__ __align__(16) float g_p [NE * NH];   // exp(logit)
__device__ __align__(16) float g_s [NN * NH];   // segment sum
__device__ __align__(16) float g_acc[NN * FH];  // message accumulator
__device__ __align__(16) float g_h [NN * NF];   // inter-layer features
__device__ __align__(16) float g_h2[NN * NF];

// ---------------- node transform: ft = x @ Wn, el/er attention dots --------
__global__ __launch_bounds__(128) void node_kernel(
        const float* __restrict__ x, const float* __restrict__ Wn,
        const float* __restrict__ al, const float* __restrict__ ar)
{
    const int c = threadIdx.x;                 // output column 0..127
    const int n0 = blockIdx.x * 16;
    float w[NF];
#pragma unroll
    for (int k = 0; k < NF; k++) w[k] = Wn[k * FH + c];   // coalesced across c
    const float alc = al[c], arc = ar[c];

    __shared__ float sx[16][NF];
#pragma unroll
    for (int i = 0; i < 8; i++) {              // 16*64 = 8*128
        int idx = i * 128 + c;
        sx[idx >> 6][idx & 63] = x[n0 * NF + idx];
    }
    __syncthreads();

    __shared__ float swl[4], swr[4];
    const int wid = c >> 5, lane = c & 31;
    for (int i = 0; i < 16; i++) {
        const int n = n0 + i;
        float f = 0.f;
#pragma unroll
        for (int k = 0; k < NF; k++) f = fmaf(sx[i][k], w[k], f);
        g_ft[n * FH + c] = f;
        float vl = f * alc, vr = f * arc;
#pragma unroll
        for (int o = 16; o; o >>= 1) {
            vl += __shfl_down_sync(0xffffffffu, vl, o);
            vr += __shfl_down_sync(0xffffffffu, vr, o);
        }
        if (lane == 0) { swl[wid] = vl; swr[wid] = vr; }
        __syncthreads();
        if (c < NH) {
            g_el[n * NH + c] = swl[2 * c] + swl[2 * c + 1];
            g_er[n * NH + c] = swr[2 * c] + swr[2 * c + 1];
        }
        __syncthreads();
    }
}

// ---------------- edge transform: fe = ef @ We ------------------------------
#define EPB 32
__global__ __launch_bounds__(128) void edge_kernel(
        const float* __restrict__ ef, const float* __restrict__ We)
{
    const int c = threadIdx.x;
    const int e0 = blockIdx.x * EPB;
    float w[EFD];
#pragma unroll
    for (int k = 0; k < EFD; k++) w[k] = We[k * FH + c];

    __shared__ float sx[EPB][EFD];
#pragma unroll
    for (int i = 0; i < EPB * EFD / 128; i++) {
        int idx = i * 128 + c;
        sx[idx >> 5][idx & 31] = ef[e0 * EFD + idx];
    }
    __syncthreads();

#pragma unroll 4
    for (int i = 0; i < EPB; i++) {
        float f = 0.f;
#pragma unroll
        for (int k = 0; k < EFD; k++) f = fmaf(sx[i][k], w[k], f);
        g_fe[(e0 + i) * FH + c] = f;
    }
}

// ---------------- per-layer init -------------------------------------------
__global__ void init_kernel()
{
    const int i = blockIdx.x * blockDim.x + threadIdx.x;
    if (i < NN * FH) g_acc[i] = 0.f;
    if (i < NN * NH) g_s[i] = 0.f;
}

// ---------------- attention: logits -> exp -> segment sum (no max shift) ----
// ee[e,h] computed directly via reduced weight we_red[k][h] = sum_d We[k,h*64+d]*ae[h*64+d]
__global__ __launch_bounds__(256) void att_kernel(
        const float* __restrict__ ef, const float* __restrict__ We,
        const float* __restrict__ ae,
        const int* __restrict__ src, const int* __restrict__ dst)
{
    __shared__ float swr[EFD][NH];
    const int t = threadIdx.x;
    if (t < EFD * NH) {
        const int k = t >> 1, h = t & 1;
        float v = 0.f;
#pragma unroll
        for (int d = 0; d < DH; d++) v = fmaf(We[k * FH + h * DH + d], ae[h * DH + d], v);
        swr[k][h] = v;
    }
    __syncthreads();

    const int e = blockIdx.x * blockDim.x + t;
    if (e >= NE) return;
    const int sn = src[e], dn = dst[e];

    const float4* efr = (const float4*)(ef + (size_t)e * EFD);
    float ee0 = 0.f, ee1 = 0.f;
#pragma unroll
    for (int q = 0; q < EFD / 4; q++) {
        float4 v = __ldg(&efr[q]);
        ee0 = fmaf(v.x, swr[4*q+0][0], ee0); ee1 = fmaf(v.x, swr[4*q+0][1], ee1);
        ee0 = fmaf(v.y, swr[4*q+1][0], ee0); ee1 = fmaf(v.y, swr[4*q+1][1], ee1);
        ee0 = fmaf(v.z, swr[4*q+2][0], ee0); ee1 = fmaf(v.z, swr[4*q+2][1], ee1);
        ee0 = fmaf(v.w, swr[4*q+3][0], ee0); ee1 = fmaf(v.w, swr[4*q+3][1], ee1);
    }
    const float2 el2 = *(const float2*)&g_el[sn * NH];
    const float2 er2 = *(const float2*)&g_er[dn * NH];
    float l0 = el2.x + er2.x + ee0;
    float l1 = el2.y + er2.y + ee1;
    l0 = (l0 > 0.f) ? l0 : 0.2f * l0;
    l1 = (l1 > 0.f) ? l1 : 0.2f * l1;
    const float p0 = __expf(l0), p1 = __expf(l1);
    *(float2*)&g_p[e * NH] = make_float2(p0, p1);
    float* sp = &g_s[dn * NH];
    asm volatile("red.global.add.v2.f32 [%0], {%1,%2};" :: "l"(sp), "f"(p0), "f"(p1) : "memory");
}

// ---------------- message scatter: one warp per edge, float4 reductions -----
__global__ __launch_bounds__(256) void msg_kernel(
        const int* __restrict__ src, const int* __restrict__ dst)
{
    const int gw = (blockIdx.x * blockDim.x + threadIdx.x) >> 5;   // edge
    if (gw >= NE) return;
    const int lane = threadIdx.x & 31;
    const int sn = src[gw], dn = dst[gw];

    const float2 p2 = *(const float2*)&g_p[gw * NH];
    const float2 s2 = *(const float2*)&g_s[dn * NH];
    const float a = (lane < 16) ? (p2.x / s2.x) : (p2.y / s2.y);

    const float4 ft4 = __ldg((const float4*)&g_ft[(size_t)sn * FH + lane * 4]);
    const float4 fe4 = __ldg((const float4*)&g_fe[(size_t)gw * FH + lane * 4]);
    const float vx = (ft4.x + fe4.x) * a;
    const float vy = (ft4.y + fe4.y) * a;
    const float vz = (ft4.z + fe4.z) * a;
    const float vw = (ft4.w + fe4.w) * a;
    float* ap = &g_acc[(size_t)dn * FH + lane * 4];
    asm volatile("red.global.add.v4.f32 [%0], {%1,%2,%3,%4};"
                 :: "l"(ap), "f"(vx), "f"(vy), "f"(vz), "f"(vw) : "memory");
}

// ---------------- finalize: + bias, mean over heads -------------------------
__global__ void fin_kernel(const float* __restrict__ b, float* __restrict__ hout)
{
    const int i = blockIdx.x * blockDim.x + threadIdx.x;   // n*64 + d
    if (i >= NN * DH) return;
    const int n = i >> 6, d = i & 63;
    hout[i] = 0.5f * ((g_acc[n * FH + d] + b[d]) +
                      (g_acc[n * FH + 64 + d] + b[64 + d]));
}

// ---------------- encoder-to-decoder: h @ W^T (W is [64,64] row-major) ------
__global__ __launch_bounds__(64) void e2d_kernel(
        const float* __restrict__ hin, const float* __restrict__ W,
        float* __restrict__ hout)
{
    const int j = threadIdx.x;                 // 0..63
    const int n0 = blockIdx.x * 16;
    float w[64];
#pragma unroll
    for (int k = 0; k < 64; k++) w[k] = W[j * 64 + k];
    __shared__ float sx[16][64];
    for (int i = j; i < 16 * 64; i += 64)
        sx[i >> 6][i & 63] = hin[n0 * 64 + i];
    __syncthreads();
    for (int i = 0; i < 16; i++) {
        float acc = 0.f;
#pragma unroll
        for (int k = 0; k < 64; k++) acc = fmaf(sx[i][k], w[k], acc);
        hout[(n0 + i) * 64 + j] = acc;
    }
}

// ---------------- host-side driver ------------------------------------------
static void run_layer(const float* xin, const float* ef,
                      const int* src, const int* dst,
                      const float* Wn, const float* We,
                      const float* al, const float* ar,
                      const float* ae, const float* b, float* hout)
{
    node_kernel<<<NN / 16, 128>>>(xin, Wn, al, ar);
    edge_kernel<<<NE / EPB, 128>>>(ef, We);
    init_kernel<<<(NN * FH + 255) / 256, 256>>>();
    att_kernel<<<(NE + 255) / 256, 256>>>(ef, We, ae, src, dst);
    msg_kernel<<<(NE * 32 + 255) / 256, 256>>>(src, dst);
    fin_kernel<<<(NN * DH + 255) / 256, 256>>>(b, hout);
}

extern "C" void kernel_launch(void* const* d_in, const int* in_sizes, int n_in,
                              void* d_out, int out_size)
{
    const float* x   = (const float*)d_in[0];
    const float* e   = (const float*)d_in[1];
    const int*   src = (const int*)  d_in[2];
    const int*   dst = (const int*)  d_in[3];

    // Only the LAST snapshot contributes to the output (decoded[-1]).
    const int S = in_sizes[0] / (NN * NF);
    const float* xs = x   + (size_t)(S - 1) * NN * NF;
    const float* es = e   + (size_t)(S - 1) * NE * EFD;
    const int*   ss = src + (size_t)(S - 1) * NE;
    const int*   ds = dst + (size_t)(S - 1) * NE;

    void *ph = nullptr, *ph2 = nullptr;
    cudaGetSymbolAddress(&ph,  g_h);
    cudaGetSymbolAddress(&ph2, g_h2);
    float* h  = (float*)ph;
    float* h2 = (float*)ph2;

    // Input order (setup_inputs dict insertion order):
    //   0:x 1:e 2:src 3:dst, 4..9:enc0, 10..15:enc1, 16..21:dec0, 22..27:dec1, 28:W_e2d
    run_layer(xs, es, ss, ds,
              (const float*)d_in[4],  (const float*)d_in[5],
              (const float*)d_in[6],  (const float*)d_in[7],
              (const float*)d_in[8],  (const float*)d_in[9],  h);
    run_layer(h, es, ss, ds,
              (const float*)d_in[10], (const float*)d_in[11],
              (const float*)d_in[12], (const float*)d_in[13],
              (const float*)d_in[14], (const float*)d_in[15], h2);
    e2d_kernel<<<NN / 16, 64>>>(h2, (const float*)d_in[28], h);
    run_layer(h, es, ss, ds,
              (const float*)d_in[16], (const float*)d_in[17],
              (const float*)d_in[18], (const float*)d_in[19],
              (const float*)d_in[20], (const float*)d_in[21], h2);
    run_layer(h2, es, ss, ds,
              (const float*)d_in[22], (const float*)d_in[23],
              (const float*)d_in[24], (const float*)d_in[25],
              (const float*)d_in[26], (const float*)d_in[27], (float*)d_out);
}